// round 15
// baseline (speedup 1.0000x reference)
#include <cuda_runtime.h>
#include <cuda_bf16.h>
#include <math.h>
#include <stdint.h>

// Problem constants
#define NG   512
#define KK   16
#define NH   256
#define NR   (NG*KK)
#define NIN  14
#define PQS  260       // p_s/q_s row stride in floats

// Scratch (no allocation allowed -> __device__ globals)
__device__ float g_h[NR * NH];
__device__ float g_pq[NR * 512];       // fused p|q, row stride 512
__device__ float g_x[NR * NH];
__device__ float g_t[NR * NH];
// Split-bf16 weights, k-major [k][n]
__device__ __nv_bfloat16 g_Wh[NH * NH];        // Wm2 (edge)
__device__ __nv_bfloat16 g_Wl[NH * NH];
__device__ __nv_bfloat16 g_Bpqh[NH * 512];     // [Wm1[:256] | Wm1[256:]]
__device__ __nv_bfloat16 g_Bpql[NH * 512];
__device__ __nv_bfloat16 g_Bu1h[NH * NH];
__device__ __nv_bfloat16 g_Bu1l[NH * NH];
__device__ __nv_bfloat16 g_Bu2h[NH * NH];
__device__ __nv_bfloat16 g_Bu2l[NH * NH];
__device__ __nv_bfloat16 g_Bo1h[NH * NH];
__device__ __nv_bfloat16 g_Bo1l[NH * NH];
__device__ float g_bpq[512];

// ===========================================================================
// PTX helpers
// ===========================================================================
__device__ __forceinline__ uint32_t smem_u32(const void* p) {
    uint32_t a;
    asm("{ .reg .u64 t; cvta.to.shared.u64 t, %1; cvt.u32.u64 %0, t; }" : "=r"(a) : "l"(p));
    return a;
}
__device__ __forceinline__ void ldsm_x4(uint32_t r[4], uint32_t addr) {
    asm volatile("ldmatrix.sync.aligned.m8n8.x4.shared.b16 {%0,%1,%2,%3}, [%4];"
                 : "=r"(r[0]), "=r"(r[1]), "=r"(r[2]), "=r"(r[3]) : "r"(addr));
}
__device__ __forceinline__ void ldsm_x4_t(uint32_t r[4], uint32_t addr) {
    asm volatile("ldmatrix.sync.aligned.m8n8.x4.trans.shared.b16 {%0,%1,%2,%3}, [%4];"
                 : "=r"(r[0]), "=r"(r[1]), "=r"(r[2]), "=r"(r[3]) : "r"(addr));
}
__device__ __forceinline__ void mma_bf16(float c[4], const uint32_t a[4], const uint32_t* b) {
    asm volatile(
        "mma.sync.aligned.m16n8k16.row.col.f32.bf16.bf16.f32 "
        "{%0,%1,%2,%3}, {%4,%5,%6,%7}, {%8,%9}, {%0,%1,%2,%3};"
        : "+f"(c[0]), "+f"(c[1]), "+f"(c[2]), "+f"(c[3])
        : "r"(a[0]), "r"(a[1]), "r"(a[2]), "r"(a[3]), "r"(b[0]), "r"(b[1]));
}
__device__ __forceinline__ void split_bf16x2(float v0, float v1, uint32_t& hi2, uint32_t& lo2) {
    asm("cvt.rn.bf16x2.f32 %0, %1, %2;" : "=r"(hi2) : "f"(v1), "f"(v0));
    float h0 = __uint_as_float(hi2 << 16);
    float h1 = __uint_as_float(hi2 & 0xffff0000u);
    float l0 = v0 - h0, l1 = v1 - h1;
    asm("cvt.rn.bf16x2.f32 %0, %1, %2;" : "=r"(lo2) : "f"(l1), "f"(l0));
}
__device__ __forceinline__ void cp_async16(uint32_t dst, const void* src) {
    asm volatile("cp.async.cg.shared.global [%0], [%1], 16;" :: "r"(dst), "l"(src) : "memory");
}
#define CP_COMMIT() asm volatile("cp.async.commit_group;" ::: "memory")
#define CP_WAIT(n)  asm volatile("cp.async.wait_group %0;" :: "n"(n) : "memory")

// ===========================================================================
// Encoder
// ===========================================================================
__global__ void encode_kernel(const float* __restrict__ towers,
                              const float* __restrict__ We,
                              const float* __restrict__ be,
                              float* __restrict__ h) {
    __shared__ float tw[NIN];
    int r = blockIdx.x;
    if (threadIdx.x < NIN) tw[threadIdx.x] = towers[r * NIN + threadIdx.x];
    __syncthreads();
    int c = threadIdx.x;
    float acc = be[c];
#pragma unroll
    for (int d = 0; d < NIN; ++d)
        acc = fmaf(tw[d], We[d * NH + c], acc);
    h[r * NH + c] = acc;
}

// ===========================================================================
// Fused prep: split all weights into hi/lo bf16, k-major. grid = 1536 blocks.
// ===========================================================================
__global__ void prep_all(const float* __restrict__ Wm1, const float* __restrict__ bm1,
                         const float* __restrict__ Wm2, const float* __restrict__ Wu1,
                         const float* __restrict__ Wu2, const float* __restrict__ Wo1) {
    int b = blockIdx.x;
    int t = threadIdx.x;
    if (b < 512) {                     // pq fused weight [k][512]
        int idx = b * 256 + t;
        int k = idx >> 9, n = idx & 511;
        float w = (n < 256) ? Wm1[k * 256 + n] : Wm1[(256 + k) * 256 + (n - 256)];
        __nv_bfloat16 hi = __float2bfloat16(w);
        g_Bpqh[idx] = hi;
        g_Bpql[idx] = __float2bfloat16(w - __bfloat162float(hi));
        if (idx < 512) g_bpq[idx] = (idx < 256) ? bm1[idx] : 0.0f;
        return;
    }
    int which = (b - 512) >> 8;        // 0..3
    int idx = ((b - 512) & 255) * 256 + t;
    const float* W = (which == 0) ? Wm2 : (which == 1) ? Wu1 : (which == 2) ? Wu2 : Wo1;
    __nv_bfloat16* dh = (which == 0) ? g_Wh : (which == 1) ? g_Bu1h : (which == 2) ? g_Bu2h : g_Bo1h;
    __nv_bfloat16* dl = (which == 0) ? g_Wl : (which == 1) ? g_Bu1l : (which == 2) ? g_Bu2l : g_Bo1l;
    float w = W[idx];
    __nv_bfloat16 hi = __float2bfloat16(w);
    dh[idx] = hi;
    dl[idx] = __float2bfloat16(w - __bfloat162float(hi));
}

// ===========================================================================
// Wide-tile HMMA GEMM (edge-v7 inner loop): C = (relu?) A[Mx256]@B[256xN]+bias
// BM=64, BN=256, 8 warps (2m x 4n), warp tile 32x64. Dynamic smem 80KB,
// 2 CTAs/SM. A per-chunk double-buffered (load fp32 -> split bf16),
// W streamed via cp.async double buffer (512B swizzled rows).
// ===========================================================================
#define GV_A(b) ((b) * 8192)               // hi 4096 + lo 4096 per buf
#define GV_W(b) (16384 + (b) * 32768)      // hi 16384 + lo 16384 per buf
#define GV_TOT  81920

__device__ __forceinline__ void gemm_issueW(uint32_t sb, int slot, int ck, int tid,
                                            const __nv_bfloat16* Bh,
                                            const __nv_bfloat16* Bl,
                                            int ldn, int n0) {
    const int k = tid >> 3;                 // 32 rows, 8 threads/row
    const int c8 = tid & 7;
#pragma unroll
    for (int s = 0; s < 4; ++s) {
        int c16 = c8 + s * 8;               // 0..31 (16B col groups)
        uint32_t dst = sb + GV_W(slot) + (uint32_t)(k * 512 + ((c16 ^ (k & 7)) << 4));
        int gi = (ck * 32 + k) * ldn + n0 + c16 * 8;
        cp_async16(dst, (const char*)Bh + gi * 2);
        cp_async16(dst + 16384, (const char*)Bl + gi * 2);
    }
    CP_COMMIT();
}

__global__ __launch_bounds__(256, 2) void hmma_gemm(
    const float* __restrict__ A,
    const __nv_bfloat16* __restrict__ Bh, const __nv_bfloat16* __restrict__ Bl,
    const float* __restrict__ bias, float* __restrict__ C, int ldn, int relu)
{
    extern __shared__ __align__(128) char smem[];
    const uint32_t sb = smem_u32(smem);

    const int tid = threadIdx.x;
    const int wid = tid >> 5;
    const int lane = tid & 31;
    const int warp_m = wid >> 2;   // 0..1
    const int warp_n = wid & 3;    // 0..3 (64 cols each)
    const int n0 = blockIdx.x * 256;
    const int m0 = blockIdx.y * 64;

    // ---- issue W chunks 0,1 immediately
    gemm_issueW(sb, 0, 0, tid, Bh, Bl, ldn, n0);
    gemm_issueW(sb, 1, 1, tid, Bh, Bl, ldn, n0);

    // A build mapping: 4 threads per row (row = tid>>2, k-part = (tid&3)*8)
    const int arow = tid >> 2;
    const int kpart = (tid & 3) << 3;
    const int aswz = (arow >> 1) & 3;
    const uint32_t abase = (uint32_t)(arow * 64);
    const float* Arow = A + (m0 + arow) * 256;

    auto buildA = [&](int ck, int buf) {
#pragma unroll
        for (int k4 = 0; k4 < 2; ++k4) {
            int k = kpart + k4 * 4;
            float4 av = *(const float4*)&Arow[ck * 32 + k];
            uint32_t h0, l0, h1, l1;
            split_bf16x2(av.x, av.y, h0, l0);
            split_bf16x2(av.z, av.w, h1, l1);
            uint32_t byte = abase + (((k >> 3) ^ aswz) << 4) + ((k & 7) << 1);
            *(uint2*)(smem + GV_A(buf) + byte) = make_uint2(h0, h1);
            *(uint2*)(smem + GV_A(buf) + 4096 + byte) = make_uint2(l0, l1);
        }
    };

    buildA(0, 0);
    CP_WAIT(1);        // W0 complete
    __syncthreads();   // publish A0 + W0

    float acc[2][8][4];
#pragma unroll
    for (int mi = 0; mi < 2; ++mi)
#pragma unroll
        for (int ni = 0; ni < 8; ++ni)
#pragma unroll
            for (int v = 0; v < 4; ++v) acc[mi][ni][v] = 0.0f;

#pragma unroll 1
    for (int t = 0; t < 8; ++t) {
        const int buf = t & 1;
        const uint32_t aH = sb + GV_A(buf);
        const uint32_t aL = aH + 4096;
        const uint32_t wH = sb + GV_W(buf);
        const uint32_t wL = wH + 16384;

#pragma unroll
        for (int ks = 0; ks < 2; ++ks) {
            uint32_t ah[2][4], al[2][4], w[16];
#pragma unroll
            for (int mi = 0; mi < 2; ++mi) {
                int r = warp_m * 32 + mi * 16 + (lane & 15);
                int ch = ks * 2 + (lane >> 4);
                uint32_t off = r * 64 + ((ch ^ ((r >> 1) & 3)) << 4);
                ldsm_x4(ah[mi], aH + off);
                ldsm_x4(al[mi], aL + off);
            }
#pragma unroll
            for (int nb = 0; nb < 4; ++nb) {
                int kr = ks * 16 + (lane & 15);
                int ch = warp_n * 8 + nb * 2 + (lane >> 4);
                ldsm_x4_t(w + nb * 4, wH + kr * 512 + ((ch ^ (kr & 7)) << 4));
            }
#pragma unroll
            for (int mi = 0; mi < 2; ++mi)
#pragma unroll
                for (int ni = 0; ni < 8; ++ni)
                    mma_bf16(acc[mi][ni], ah[mi], w + ni * 2);
#pragma unroll
            for (int mi = 0; mi < 2; ++mi)
#pragma unroll
                for (int ni = 0; ni < 8; ++ni)
                    mma_bf16(acc[mi][ni], al[mi], w + ni * 2);
#pragma unroll
            for (int nb = 0; nb < 4; ++nb) {
                int kr = ks * 16 + (lane & 15);
                int ch = warp_n * 8 + nb * 2 + (lane >> 4);
                ldsm_x4_t(w + nb * 4, wL + kr * 512 + ((ch ^ (kr & 7)) << 4));
            }
#pragma unroll
            for (int mi = 0; mi < 2; ++mi)
#pragma unroll
                for (int ni = 0; ni < 8; ++ni)
                    mma_bf16(acc[mi][ni], ah[mi], w + ni * 2);
        }

        if (t < 7) {
            buildA(t + 1, buf ^ 1);
            CP_WAIT(0);        // W(t+1) complete
            __syncthreads();   // retire reads of buf; publish A(t+1)+W(t+1)
            if (t < 6)
                gemm_issueW(sb, buf, t + 2, tid, Bh, Bl, ldn, n0);
        }
    }

    // ---- epilogue
    const int g = lane >> 2;
    const int cq = lane & 3;
#pragma unroll
    for (int mi = 0; mi < 2; ++mi) {
        int row0 = m0 + warp_m * 32 + mi * 16 + g;
#pragma unroll
        for (int ni = 0; ni < 8; ++ni) {
            int cl = warp_n * 64 + ni * 8 + cq * 2;
            float b0 = 0.0f, b1 = 0.0f;
            if (bias) {
                float2 bv = *(const float2*)&bias[n0 + cl];
                b0 = bv.x; b1 = bv.y;
            }
            float v0 = acc[mi][ni][0] + b0;
            float v1 = acc[mi][ni][1] + b1;
            float v2 = acc[mi][ni][2] + b0;
            float v3 = acc[mi][ni][3] + b1;
            if (relu) {
                v0 = fmaxf(v0, 0.0f); v1 = fmaxf(v1, 0.0f);
                v2 = fmaxf(v2, 0.0f); v3 = fmaxf(v3, 0.0f);
            }
            *(float2*)(C + row0 * ldn + n0 + cl) = make_float2(v0, v1);
            *(float2*)(C + (row0 + 8) * ldn + n0 + cl) = make_float2(v2, v3);
        }
    }
}

// ===========================================================================
// Edge kernel v7 (unchanged from passing R14): wide warp tile (32x64),
// N=256 in ONE pass -> 8 chunks. CTA = (graph, i-quarter), 2 CTAs/SM.
// ===========================================================================
#define E7_P    0                          // [4][260] f32 = 4160
#define E7_Q    4224                       // [16][260] f32 -> end 20864
#define E7_A(b) (21504 + (b) * 8192)       // hi 4096 + lo 4096 per buf
#define E7_W(b) (37888 + (b) * 32768)      // hi 16384 + lo 16384 per buf
#define E7_TOT  103424

__device__ __forceinline__ void edge_issueW(uint32_t sb, int slot, int ck, int tid) {
    const int k = tid >> 3;
    const int c8 = tid & 7;
#pragma unroll
    for (int s = 0; s < 4; ++s) {
        int c16 = c8 + s * 8;
        uint32_t dst = sb + E7_W(slot) + (uint32_t)(k * 512 + ((c16 ^ (k & 7)) << 4));
        int gi = (ck * 32 + k) * NH + c16 * 8;
        cp_async16(dst, (const char*)g_Wh + gi * 2);
        cp_async16(dst + 16384, (const char*)g_Wl + gi * 2);
    }
    CP_COMMIT();
}

__global__ __launch_bounds__(256, 2) void edge_mma_kernel(
    const float* __restrict__ pq,
    const float* __restrict__ bm2,
    const float* __restrict__ h, float* __restrict__ x)
{
    extern __shared__ __align__(128) char smem[];
    const uint32_t sb = smem_u32(smem);
    float* p_s = (float*)(smem + E7_P);
    float* q_s = (float*)(smem + E7_Q);

    const int n = blockIdx.x;
    const int iq = blockIdx.y;
    const int tid = threadIdx.x;
    const int wid = tid >> 5;
    const int lane = tid & 31;
    const int warp_m = wid >> 2;
    const int warp_n = wid & 3;

    edge_issueW(sb, 0, 0, tid);
    edge_issueW(sb, 1, 1, tid);

    {
        const float4* pg = (const float4*)(pq + (n * KK + iq * 4) * 512);
        const float4* qg = (const float4*)(pq + n * KK * 512 + 256);
        {
            int r = tid >> 6, c4 = tid & 63;
            *(float4*)&p_s[r * PQS + c4 * 4] = pg[r * 128 + c4];
        }
#pragma unroll
        for (int s = 0; s < 4; ++s) {
            int idx = s * 256 + tid;
            int r = idx >> 6, c4 = idx & 63;
            *(float4*)&q_s[r * PQS + c4 * 4] = qg[r * 128 + c4];
        }
    }
    __syncthreads();

    const int arow = tid >> 2;
    const int kpart = (tid & 3) << 3;
    const float* prow = p_s + (arow >> 4) * PQS;
    const float* qrow = q_s + (arow & 15) * PQS;
    const int aswz = (arow >> 1) & 3;
    const uint32_t abase = (uint32_t)(arow * 64);

    auto buildA = [&](int ck, int buf) {
#pragma unroll
        for (int k4 = 0; k4 < 2; ++k4) {
            int k = kpart + k4 * 4;
            int kg = ck * 32 + k;
            float4 pv = *(const float4*)&prow[kg];
            float4 qv = *(const float4*)&qrow[kg];
            float v0 = fmaxf(pv.x + qv.x, 0.0f);
            float v1 = fmaxf(pv.y + qv.y, 0.0f);
            float v2 = fmaxf(pv.z + qv.z, 0.0f);
            float v3 = fmaxf(pv.w + qv.w, 0.0f);
            uint32_t h0, l0, h1, l1;
            split_bf16x2(v0, v1, h0, l0);
            split_bf16x2(v2, v3, h1, l1);
            uint32_t byte = abase + (((k >> 3) ^ aswz) << 4) + ((k & 7) << 1);
            *(uint2*)(smem + E7_A(buf) + byte) = make_uint2(h0, h1);
            *(uint2*)(smem + E7_A(buf) + 4096 + byte) = make_uint2(l0, l1);
        }
    };

    buildA(0, 0);
    CP_WAIT(1);
    __syncthreads();

    float acc[2][8][4];
#pragma unroll
    for (int mi = 0; mi < 2; ++mi)
#pragma unroll
        for (int ni = 0; ni < 8; ++ni)
#pragma unroll
            for (int v = 0; v < 4; ++v) acc[mi][ni][v] = 0.0f;

#pragma unroll 1
    for (int t = 0; t < 8; ++t) {
        const int buf = t & 1;
        const uint32_t aH = sb + E7_A(buf);
        const uint32_t aL = aH + 4096;
        const uint32_t wH = sb + E7_W(buf);
        const uint32_t wL = wH + 16384;

#pragma unroll
        for (int ks = 0; ks < 2; ++ks) {
            uint32_t ah[2][4], al[2][4], w[16];
#pragma unroll
            for (int mi = 0; mi < 2; ++mi) {
                int r = warp_m * 32 + mi * 16 + (lane & 15);
                int ch = ks * 2 + (lane >> 4);
                uint32_t off = r * 64 + ((ch ^ ((r >> 1) & 3)) << 4);
                ldsm_x4(ah[mi], aH + off);
                ldsm_x4(al[mi], aL + off);
            }
#pragma unroll
            for (int nb = 0; nb < 4; ++nb) {
                int kr = ks * 16 + (lane & 15);
                int ch = warp_n * 8 + nb * 2 + (lane >> 4);
                ldsm_x4_t(w + nb * 4, wH + kr * 512 + ((ch ^ (kr & 7)) << 4));
            }
#pragma unroll
            for (int mi = 0; mi < 2; ++mi)
#pragma unroll
                for (int ni = 0; ni < 8; ++ni)
                    mma_bf16(acc[mi][ni], ah[mi], w + ni * 2);
#pragma unroll
            for (int mi = 0; mi < 2; ++mi)
#pragma unroll
                for (int ni = 0; ni < 8; ++ni)
                    mma_bf16(acc[mi][ni], al[mi], w + ni * 2);
#pragma unroll
            for (int nb = 0; nb < 4; ++nb) {
                int kr = ks * 16 + (lane & 15);
                int ch = warp_n * 8 + nb * 2 + (lane >> 4);
                ldsm_x4_t(w + nb * 4, wL + kr * 512 + ((ch ^ (kr & 7)) << 4));
            }
#pragma unroll
            for (int mi = 0; mi < 2; ++mi)
#pragma unroll
                for (int ni = 0; ni < 8; ++ni)
                    mma_bf16(acc[mi][ni], ah[mi], w + ni * 2);
        }

        if (t < 7) {
            buildA(t + 1, buf ^ 1);
            CP_WAIT(0);
            __syncthreads();
            if (t < 6)
                edge_issueW(sb, buf, t + 2, tid);
        }
    }

    const int g = lane >> 2;
    const int cq = lane & 3;
#pragma unroll
    for (int mi = 0; mi < 2; ++mi) {
        const int i_node = iq * 4 + warp_m * 2 + mi;
        float s0[8], s1[8];
#pragma unroll
        for (int ni = 0; ni < 8; ++ni) {
            int col = warp_n * 64 + ni * 8 + cq * 2;
            float2 bv = *(const float2*)&bm2[col];
            float e0 = fmaxf(acc[mi][ni][0] + bv.x, 0.0f);
            float e1 = fmaxf(acc[mi][ni][1] + bv.y, 0.0f);
            float e2 = fmaxf(acc[mi][ni][2] + bv.x, 0.0f);
            float e3 = fmaxf(acc[mi][ni][3] + bv.y, 0.0f);
            if (g == i_node)     { e0 = 0.0f; e1 = 0.0f; }
            if (g + 8 == i_node) { e2 = 0.0f; e3 = 0.0f; }
            s0[ni] = e0 + e2;
            s1[ni] = e1 + e3;
        }
#pragma unroll
        for (int ni = 0; ni < 8; ++ni) {
#pragma unroll
            for (int m = 4; m <= 16; m <<= 1) {
                s0[ni] += __shfl_xor_sync(0xffffffffu, s0[ni], m);
                s1[ni] += __shfl_xor_sync(0xffffffffu, s1[ni], m);
            }
        }
        if (lane < 4) {
            int row = n * KK + i_node;
#pragma unroll
            for (int ni = 0; ni < 8; ++ni) {
                int col = warp_n * 64 + ni * 8 + lane * 2;
                const float2 hv = *(const float2*)(h + row * NH + col);
                *(float2*)(x + row * NH + col) = make_float2(hv.x + s0[ni], hv.y + s1[ni]);
            }
        }
    }
}

// ===========================================================================
// Output head
// ===========================================================================
__global__ void out_kernel(const float* __restrict__ t,
                           const float* __restrict__ Wo2,
                           const float* __restrict__ bo2,
                           float* __restrict__ out) {
    __shared__ float sig[16];
    const int n = blockIdx.x;
    const int w = threadIdx.x >> 5;
    const int l = threadIdx.x & 31;
    const float* row = t + (n * KK + w) * NH;
    float acc = 0.0f;
#pragma unroll
    for (int kk = l; kk < NH; kk += 32)
        acc = fmaf(row[kk], Wo2[kk], acc);
#pragma unroll
    for (int m = 16; m; m >>= 1)
        acc += __shfl_xor_sync(0xffffffffu, acc, m);
    if (l == 0) {
        float logit = acc + bo2[0];
        sig[w] = 1.0f / (1.0f + expf(-logit));
    }
    __syncthreads();
    if (threadIdx.x == 0) {
        float prodv = 1.0f;
#pragma unroll
        for (int i2 = 0; i2 < 16; ++i2) prodv *= sig[i2];
        out[n] = prodv;
    }
}

// ===========================================================================
extern "C" void kernel_launch(void* const* d_in, const int* in_sizes, int n_in,
                              void* d_out, int out_size) {
    const float* towers = (const float*)d_in[0];
    const float* We  = (const float*)d_in[1];
    const float* be  = (const float*)d_in[2];
    const float* Wm1 = (const float*)d_in[3];
    const float* bm1 = (const float*)d_in[4];
    const float* Wm2 = (const float*)d_in[5];
    const float* bm2 = (const float*)d_in[6];
    const float* Wu1 = (const float*)d_in[7];
    const float* bu1 = (const float*)d_in[8];
    const float* Wu2 = (const float*)d_in[9];
    const float* bu2 = (const float*)d_in[10];
    const float* Wo1 = (const float*)d_in[11];
    const float* bo1 = (const float*)d_in[12];
    const float* Wo2 = (const float*)d_in[13];
    const float* bo2 = (const float*)d_in[14];
    float* out = (float*)d_out;

    float *h, *pq, *x, *t, *bpq;
    __nv_bfloat16 *Bpqh, *Bpql, *Bu1h, *Bu1l, *Bu2h, *Bu2l, *Bo1h, *Bo1l;
    cudaGetSymbolAddress((void**)&h, g_h);
    cudaGetSymbolAddress((void**)&pq, g_pq);
    cudaGetSymbolAddress((void**)&x, g_x);
    cudaGetSymbolAddress((void**)&t, g_t);
    cudaGetSymbolAddress((void**)&bpq, g_bpq);
    cudaGetSymbolAddress((void**)&Bpqh, g_Bpqh);
    cudaGetSymbolAddress((void**)&Bpql, g_Bpql);
    cudaGetSymbolAddress((void**)&Bu1h, g_Bu1h);
    cudaGetSymbolAddress((void**)&Bu1l, g_Bu1l);
    cudaGetSymbolAddress((void**)&Bu2h, g_Bu2h);
    cudaGetSymbolAddress((void**)&Bu2l, g_Bu2l);
    cudaGetSymbolAddress((void**)&Bo1h, g_Bo1h);
    cudaGetSymbolAddress((void**)&Bo1l, g_Bo1l);

    cudaFuncSetAttribute(edge_mma_kernel,
                         cudaFuncAttributeMaxDynamicSharedMemorySize, E7_TOT);
    cudaFuncSetAttribute(hmma_gemm,
                         cudaFuncAttributeMaxDynamicSharedMemorySize, GV_TOT);

    prep_all<<<1536, 256>>>(Wm1, bm1, Wm2, Wu1, Wu2, Wo1);
    encode_kernel<<<NR, 256>>>(towers, We, be, h);

    for (int it = 0; it < 3; ++it) {
        // pq = h @ [Wm1_s | Wm1_r] + [bm1|0]   (M=8192, N=512, BN=256)
        hmma_gemm<<<dim3(2, 128), 256, GV_TOT>>>(h, Bpqh, Bpql, bpq, pq, 512, 0);
        // x = h + masked edge sum
        edge_mma_kernel<<<dim3(NG, 4), 256, E7_TOT>>>(pq, bm2, h, x);
        // h = relu(x@Wu1+bu1) @ Wu2 + bu2   (N=256, single col tile)
        hmma_gemm<<<dim3(1, 128), 256, GV_TOT>>>(x, Bu1h, Bu1l, bu1, t, 256, 1);
        hmma_gemm<<<dim3(1, 128), 256, GV_TOT>>>(t, Bu2h, Bu2l, bu2, h, 256, 0);
    }
    hmma_gemm<<<dim3(1, 128), 256, GV_TOT>>>(h, Bo1h, Bo1l, bo1, t, 256, 1);
    out_kernel<<<NG, 512>>>(t, Wo2, bo2, out);
}

// round 16
// speedup vs baseline: 1.0089x; 1.0089x over previous
#include <cuda_runtime.h>
#include <cuda_bf16.h>
#include <math.h>
#include <stdint.h>

// Problem constants
#define NG   512
#define KK   16
#define NH   256
#define NR   (NG*KK)
#define NIN  14
#define PQS  260       // p_s/q_s row stride in floats

// Scratch (no allocation allowed -> __device__ globals)
__device__ float g_h[NR * NH];
__device__ float g_pq[NR * 512];       // fused p|q, row stride 512
__device__ float g_x[NR * NH];
__device__ float g_t[NR * NH];
// Split-bf16 weights, k-major [k][n]
__device__ __nv_bfloat16 g_Wh[NH * NH];        // Wm2 (edge)
__device__ __nv_bfloat16 g_Wl[NH * NH];
__device__ __nv_bfloat16 g_Bpqh[NH * 512];     // [Wm1[:256] | Wm1[256:]]
__device__ __nv_bfloat16 g_Bpql[NH * 512];
__device__ __nv_bfloat16 g_Bu1h[NH * NH];
__device__ __nv_bfloat16 g_Bu1l[NH * NH];
__device__ __nv_bfloat16 g_Bu2h[NH * NH];
__device__ __nv_bfloat16 g_Bu2l[NH * NH];
__device__ __nv_bfloat16 g_Bo1h[NH * NH];
__device__ __nv_bfloat16 g_Bo1l[NH * NH];
__device__ float g_bpq[512];

// ===========================================================================
// PTX helpers
// ===========================================================================
__device__ __forceinline__ uint32_t smem_u32(const void* p) {
    uint32_t a;
    asm("{ .reg .u64 t; cvta.to.shared.u64 t, %1; cvt.u32.u64 %0, t; }" : "=r"(a) : "l"(p));
    return a;
}
__device__ __forceinline__ void ldsm_x4(uint32_t r[4], uint32_t addr) {
    asm volatile("ldmatrix.sync.aligned.m8n8.x4.shared.b16 {%0,%1,%2,%3}, [%4];"
                 : "=r"(r[0]), "=r"(r[1]), "=r"(r[2]), "=r"(r[3]) : "r"(addr));
}
__device__ __forceinline__ void ldsm_x4_t(uint32_t r[4], uint32_t addr) {
    asm volatile("ldmatrix.sync.aligned.m8n8.x4.trans.shared.b16 {%0,%1,%2,%3}, [%4];"
                 : "=r"(r[0]), "=r"(r[1]), "=r"(r[2]), "=r"(r[3]) : "r"(addr));
}
__device__ __forceinline__ void mma_bf16(float c[4], const uint32_t a[4], const uint32_t* b) {
    asm volatile(
        "mma.sync.aligned.m16n8k16.row.col.f32.bf16.bf16.f32 "
        "{%0,%1,%2,%3}, {%4,%5,%6,%7}, {%8,%9}, {%0,%1,%2,%3};"
        : "+f"(c[0]), "+f"(c[1]), "+f"(c[2]), "+f"(c[3])
        : "r"(a[0]), "r"(a[1]), "r"(a[2]), "r"(a[3]), "r"(b[0]), "r"(b[1]));
}
__device__ __forceinline__ void split_bf16x2(float v0, float v1, uint32_t& hi2, uint32_t& lo2) {
    asm("cvt.rn.bf16x2.f32 %0, %1, %2;" : "=r"(hi2) : "f"(v1), "f"(v0));
    float h0 = __uint_as_float(hi2 << 16);
    float h1 = __uint_as_float(hi2 & 0xffff0000u);
    float l0 = v0 - h0, l1 = v1 - h1;
    asm("cvt.rn.bf16x2.f32 %0, %1, %2;" : "=r"(lo2) : "f"(l1), "f"(l0));
}
__device__ __forceinline__ void cp_async16(uint32_t dst, const void* src) {
    asm volatile("cp.async.cg.shared.global [%0], [%1], 16;" :: "r"(dst), "l"(src) : "memory");
}
#define CP_COMMIT() asm volatile("cp.async.commit_group;" ::: "memory")
#define CP_WAIT(n)  asm volatile("cp.async.wait_group %0;" :: "n"(n) : "memory")

// ===========================================================================
// Fused prep + encode: blocks [0,1536) do weight splitting; [1536, 1536+8192)
// do the encoder (one row each).
// ===========================================================================
__global__ void prep_encode_kernel(
    const float* __restrict__ Wm1, const float* __restrict__ bm1,
    const float* __restrict__ Wm2, const float* __restrict__ Wu1,
    const float* __restrict__ Wu2, const float* __restrict__ Wo1,
    const float* __restrict__ towers, const float* __restrict__ We,
    const float* __restrict__ be, float* __restrict__ h)
{
    int b = blockIdx.x;
    int t = threadIdx.x;
    if (b >= 1536) {
        // encoder
        __shared__ float tw[NIN];
        int r = b - 1536;
        if (t < NIN) tw[t] = towers[r * NIN + t];
        __syncthreads();
        float acc = be[t];
#pragma unroll
        for (int d = 0; d < NIN; ++d)
            acc = fmaf(tw[d], We[d * NH + t], acc);
        h[r * NH + t] = acc;
        return;
    }
    if (b < 512) {                     // pq fused weight [k][512]
        int idx = b * 256 + t;
        int k = idx >> 9, n = idx & 511;
        float w = (n < 256) ? Wm1[k * 256 + n] : Wm1[(256 + k) * 256 + (n - 256)];
        __nv_bfloat16 hi = __float2bfloat16(w);
        g_Bpqh[idx] = hi;
        g_Bpql[idx] = __float2bfloat16(w - __bfloat162float(hi));
        if (idx < 512) g_bpq[idx] = (idx < 256) ? bm1[idx] : 0.0f;
        return;
    }
    int which = (b - 512) >> 8;        // 0..3
    int idx = ((b - 512) & 255) * 256 + t;
    const float* W = (which == 0) ? Wm2 : (which == 1) ? Wu1 : (which == 2) ? Wu2 : Wo1;
    __nv_bfloat16* dh = (which == 0) ? g_Wh : (which == 1) ? g_Bu1h : (which == 2) ? g_Bu2h : g_Bo1h;
    __nv_bfloat16* dl = (which == 0) ? g_Wl : (which == 1) ? g_Bu1l : (which == 2) ? g_Bu2l : g_Bo1l;
    float w = W[idx];
    __nv_bfloat16 hi = __float2bfloat16(w);
    dh[idx] = hi;
    dl[idx] = __float2bfloat16(w - __bfloat162float(hi));
}

// ===========================================================================
// Wide-tile HMMA GEMM, templated on MI (m16-tiles per warp; BM = MI*32):
// C = (relu?) A[Mx256] @ B[256xN] + bias. 8 warps = 2m x 4n, warp tile
// (MI*16) x 64. A per-chunk double-buffered split-bf16; W cp.async
// double-buffered, 512B swizzled rows. 2 CTAs/SM.
// ===========================================================================
template <int MI>
__device__ __forceinline__ void gemm_issueW(uint32_t sb, int slot, int ck, int tid,
                                            const __nv_bfloat16* Bh,
                                            const __nv_bfloat16* Bl,
                                            int ldn, int n0) {
    constexpr int WOFF = 8 * MI * 2048;   // W region base (after 2 A bufs)
    const int k = tid >> 3;
    const int c8 = tid & 7;
#pragma unroll
    for (int s = 0; s < 4; ++s) {
        int c16 = c8 + s * 8;
        uint32_t dst = sb + WOFF + slot * 32768 + (uint32_t)(k * 512 + ((c16 ^ (k & 7)) << 4));
        int gi = (ck * 32 + k) * ldn + n0 + c16 * 8;
        cp_async16(dst, (const char*)Bh + gi * 2);
        cp_async16(dst + 16384, (const char*)Bl + gi * 2);
    }
    CP_COMMIT();
}

template <int MI>
__global__ __launch_bounds__(256, 2) void hmma_gemm(
    const float* __restrict__ A,
    const __nv_bfloat16* __restrict__ Bh, const __nv_bfloat16* __restrict__ Bl,
    const float* __restrict__ bias, float* __restrict__ C, int ldn, int relu)
{
    constexpr int BM   = MI * 32;
    constexpr int ABUF = BM * 64;          // bytes per split per A buf
    constexpr int WOFF = 8 * MI * 2048;    // = 4*ABUF
    extern __shared__ __align__(128) char smem[];
    const uint32_t sb = smem_u32(smem);

    const int tid = threadIdx.x;
    const int wid = tid >> 5;
    const int lane = tid & 31;
    const int warp_m = wid >> 2;   // 0..1
    const int warp_n = wid & 3;    // 0..3 (64 cols each)
    const int n0 = blockIdx.x * 256;
    const int m0 = blockIdx.y * BM;

    gemm_issueW<MI>(sb, 0, 0, tid, Bh, Bl, ldn, n0);
    gemm_issueW<MI>(sb, 1, 1, tid, Bh, Bl, ldn, n0);

    // A build mapping: tpr threads per row
    constexpr int TPR = 256 / BM;          // MI=2 -> 4, MI=1 -> 8
    constexpr int KW  = 32 / TPR;          // k-values per thread per chunk
    const int arow = tid / TPR;
    const int klane = tid % TPR;
    const int aswz = (arow >> 1) & 3;
    const uint32_t abase = (uint32_t)(arow * 64);
    const float* Arow = A + (m0 + arow) * 256;

    auto buildA = [&](int ck, int buf) {
#pragma unroll
        for (int k4 = 0; k4 < KW / 4; ++k4) {
            int k = klane * KW + k4 * 4;
            float4 av = *(const float4*)&Arow[ck * 32 + k];
            uint32_t h0, l0, h1, l1;
            split_bf16x2(av.x, av.y, h0, l0);
            split_bf16x2(av.z, av.w, h1, l1);
            uint32_t byte = abase + (((k >> 3) ^ aswz) << 4) + ((k & 7) << 1);
            *(uint2*)(smem + buf * 2 * ABUF + byte) = make_uint2(h0, h1);
            *(uint2*)(smem + buf * 2 * ABUF + ABUF + byte) = make_uint2(l0, l1);
        }
    };

    buildA(0, 0);
    CP_WAIT(1);
    __syncthreads();

    float acc[MI][8][4];
#pragma unroll
    for (int mi = 0; mi < MI; ++mi)
#pragma unroll
        for (int ni = 0; ni < 8; ++ni)
#pragma unroll
            for (int v = 0; v < 4; ++v) acc[mi][ni][v] = 0.0f;

#pragma unroll 1
    for (int t = 0; t < 8; ++t) {
        const int buf = t & 1;
        const uint32_t aH = sb + buf * 2 * ABUF;
        const uint32_t aL = aH + ABUF;
        const uint32_t wH = sb + WOFF + buf * 32768;
        const uint32_t wL = wH + 16384;

#pragma unroll
        for (int ks = 0; ks < 2; ++ks) {
            uint32_t ah[MI][4], al[MI][4], w[16];
#pragma unroll
            for (int mi = 0; mi < MI; ++mi) {
                int r = warp_m * (MI * 16) + mi * 16 + (lane & 15);
                int ch = ks * 2 + (lane >> 4);
                uint32_t off = r * 64 + ((ch ^ ((r >> 1) & 3)) << 4);
                ldsm_x4(ah[mi], aH + off);
                ldsm_x4(al[mi], aL + off);
            }
#pragma unroll
            for (int nb = 0; nb < 4; ++nb) {
                int kr = ks * 16 + (lane & 15);
                int ch = warp_n * 8 + nb * 2 + (lane >> 4);
                ldsm_x4_t(w + nb * 4, wH + kr * 512 + ((ch ^ (kr & 7)) << 4));
            }
#pragma unroll
            for (int mi = 0; mi < MI; ++mi)
#pragma unroll
                for (int ni = 0; ni < 8; ++ni)
                    mma_bf16(acc[mi][ni], ah[mi], w + ni * 2);
#pragma unroll
            for (int mi = 0; mi < MI; ++mi)
#pragma unroll
                for (int ni = 0; ni < 8; ++ni)
                    mma_bf16(acc[mi][ni], al[mi], w + ni * 2);
#pragma unroll
            for (int nb = 0; nb < 4; ++nb) {
                int kr = ks * 16 + (lane & 15);
                int ch = warp_n * 8 + nb * 2 + (lane >> 4);
                ldsm_x4_t(w + nb * 4, wL + kr * 512 + ((ch ^ (kr & 7)) << 4));
            }
#pragma unroll
            for (int mi = 0; mi < MI; ++mi)
#pragma unroll
                for (int ni = 0; ni < 8; ++ni)
                    mma_bf16(acc[mi][ni], ah[mi], w + ni * 2);
        }

        if (t < 7) {
            buildA(t + 1, buf ^ 1);
            CP_WAIT(0);
            __syncthreads();
            if (t < 6)
                gemm_issueW<MI>(sb, buf, t + 2, tid, Bh, Bl, ldn, n0);
        }
    }

    // ---- epilogue
    const int g = lane >> 2;
    const int cq = lane & 3;
#pragma unroll
    for (int mi = 0; mi < MI; ++mi) {
        int row0 = m0 + warp_m * (MI * 16) + mi * 16 + g;
#pragma unroll
        for (int ni = 0; ni < 8; ++ni) {
            int cl = warp_n * 64 + ni * 8 + cq * 2;
            float b0 = 0.0f, b1 = 0.0f;
            if (bias) {
                float2 bv = *(const float2*)&bias[n0 + cl];
                b0 = bv.x; b1 = bv.y;
            }
            float v0 = acc[mi][ni][0] + b0;
            float v1 = acc[mi][ni][1] + b1;
            float v2 = acc[mi][ni][2] + b0;
            float v3 = acc[mi][ni][3] + b1;
            if (relu) {
                v0 = fmaxf(v0, 0.0f); v1 = fmaxf(v1, 0.0f);
                v2 = fmaxf(v2, 0.0f); v3 = fmaxf(v3, 0.0f);
            }
            *(float2*)(C + row0 * ldn + n0 + cl) = make_float2(v0, v1);
            *(float2*)(C + (row0 + 8) * ldn + n0 + cl) = make_float2(v2, v3);
        }
    }
}

#define GV_TOT(MI) (8 * (MI) * 2048 + 65536)   // 2 A bufs + 2 W bufs

// ===========================================================================
// Edge kernel v7 (unchanged from passing R14/R15)
// ===========================================================================
#define E7_P    0
#define E7_Q    4224
#define E7_A(b) (21504 + (b) * 8192)
#define E7_W(b) (37888 + (b) * 32768)
#define E7_TOT  103424

__device__ __forceinline__ void edge_issueW(uint32_t sb, int slot, int ck, int tid) {
    const int k = tid >> 3;
    const int c8 = tid & 7;
#pragma unroll
    for (int s = 0; s < 4; ++s) {
        int c16 = c8 + s * 8;
        uint32_t dst = sb + E7_W(slot) + (uint32_t)(k * 512 + ((c16 ^ (k & 7)) << 4));
        int gi = (ck * 32 + k) * NH + c16 * 8;
        cp_async16(dst, (const char*)g_Wh + gi * 2);
        cp_async16(dst + 16384, (const char*)g_Wl + gi * 2);
    }
    CP_COMMIT();
}

__global__ __launch_bounds__(256, 2) void edge_mma_kernel(
    const float* __restrict__ pq,
    const float* __restrict__ bm2,
    const float* __restrict__ h, float* __restrict__ x)
{
    extern __shared__ __align__(128) char smem[];
    const uint32_t sb = smem_u32(smem);
    float* p_s = (float*)(smem + E7_P);
    float* q_s = (float*)(smem + E7_Q);

    const int n = blockIdx.x;
    const int iq = blockIdx.y;
    const int tid = threadIdx.x;
    const int wid = tid >> 5;
    const int lane = tid & 31;
    const int warp_m = wid >> 2;
    const int warp_n = wid & 3;

    edge_issueW(sb, 0, 0, tid);
    edge_issueW(sb, 1, 1, tid);

    {
        const float4* pg = (const float4*)(pq + (n * KK + iq * 4) * 512);
        const float4* qg = (const float4*)(pq + n * KK * 512 + 256);
        {
            int r = tid >> 6, c4 = tid & 63;
            *(float4*)&p_s[r * PQS + c4 * 4] = pg[r * 128 + c4];
        }
#pragma unroll
        for (int s = 0; s < 4; ++s) {
            int idx = s * 256 + tid;
            int r = idx >> 6, c4 = idx & 63;
            *(float4*)&q_s[r * PQS + c4 * 4] = qg[r * 128 + c4];
        }
    }
    __syncthreads();

    const int arow = tid >> 2;
    const int kpart = (tid & 3) << 3;
    const float* prow = p_s + (arow >> 4) * PQS;
    const float* qrow = q_s + (arow & 15) * PQS;
    const int aswz = (arow >> 1) & 3;
    const uint32_t abase = (uint32_t)(arow * 64);

    auto buildA = [&](int ck, int buf) {
#pragma unroll
        for (int k4 = 0; k4 < 2; ++k4) {
            int k = kpart + k4 * 4;
            int kg = ck * 32 + k;
            float4 pv = *(const float4*)&prow[kg];
            float4 qv = *(const float4*)&qrow[kg];
            float v0 = fmaxf(pv.x + qv.x, 0.0f);
            float v1 = fmaxf(pv.y + qv.y, 0.0f);
            float v2 = fmaxf(pv.z + qv.z, 0.0f);
            float v3 = fmaxf(pv.w + qv.w, 0.0f);
            uint32_t h0, l0, h1, l1;
            split_bf16x2(v0, v1, h0, l0);
            split_bf16x2(v2, v3, h1, l1);
            uint32_t byte = abase + (((k >> 3) ^ aswz) << 4) + ((k & 7) << 1);
            *(uint2*)(smem + E7_A(buf) + byte) = make_uint2(h0, h1);
            *(uint2*)(smem + E7_A(buf) + 4096 + byte) = make_uint2(l0, l1);
        }
    };

    buildA(0, 0);
    CP_WAIT(1);
    __syncthreads();

    float acc[2][8][4];
#pragma unroll
    for (int mi = 0; mi < 2; ++mi)
#pragma unroll
        for (int ni = 0; ni < 8; ++ni)
#pragma unroll
            for (int v = 0; v < 4; ++v) acc[mi][ni][v] = 0.0f;

#pragma unroll 1
    for (int t = 0; t < 8; ++t) {
        const int buf = t & 1;
        const uint32_t aH = sb + E7_A(buf);
        const uint32_t aL = aH + 4096;
        const uint32_t wH = sb + E7_W(buf);
        const uint32_t wL = wH + 16384;

#pragma unroll
        for (int ks = 0; ks < 2; ++ks) {
            uint32_t ah[2][4], al[2][4], w[16];
#pragma unroll
            for (int mi = 0; mi < 2; ++mi) {
                int r = warp_m * 32 + mi * 16 + (lane & 15);
                int ch = ks * 2 + (lane >> 4);
                uint32_t off = r * 64 + ((ch ^ ((r >> 1) & 3)) << 4);
                ldsm_x4(ah[mi], aH + off);
                ldsm_x4(al[mi], aL + off);
            }
#pragma unroll
            for (int nb = 0; nb < 4; ++nb) {
                int kr = ks * 16 + (lane & 15);
                int ch = warp_n * 8 + nb * 2 + (lane >> 4);
                ldsm_x4_t(w + nb * 4, wH + kr * 512 + ((ch ^ (kr & 7)) << 4));
            }
#pragma unroll
            for (int mi = 0; mi < 2; ++mi)
#pragma unroll
                for (int ni = 0; ni < 8; ++ni)
                    mma_bf16(acc[mi][ni], ah[mi], w + ni * 2);
#pragma unroll
            for (int mi = 0; mi < 2; ++mi)
#pragma unroll
                for (int ni = 0; ni < 8; ++ni)
                    mma_bf16(acc[mi][ni], al[mi], w + ni * 2);
#pragma unroll
            for (int nb = 0; nb < 4; ++nb) {
                int kr = ks * 16 + (lane & 15);
                int ch = warp_n * 8 + nb * 2 + (lane >> 4);
                ldsm_x4_t(w + nb * 4, wL + kr * 512 + ((ch ^ (kr & 7)) << 4));
            }
#pragma unroll
            for (int mi = 0; mi < 2; ++mi)
#pragma unroll
                for (int ni = 0; ni < 8; ++ni)
                    mma_bf16(acc[mi][ni], ah[mi], w + ni * 2);
        }

        if (t < 7) {
            buildA(t + 1, buf ^ 1);
            CP_WAIT(0);
            __syncthreads();
            if (t < 6)
                edge_issueW(sb, buf, t + 2, tid);
        }
    }

    const int g = lane >> 2;
    const int cq = lane & 3;
#pragma unroll
    for (int mi = 0; mi < 2; ++mi) {
        const int i_node = iq * 4 + warp_m * 2 + mi;
        float s0[8], s1[8];
#pragma unroll
        for (int ni = 0; ni < 8; ++ni) {
            int col = warp_n * 64 + ni * 8 + cq * 2;
            float2 bv = *(const float2*)&bm2[col];
            float e0 = fmaxf(acc[mi][ni][0] + bv.x, 0.0f);
            float e1 = fmaxf(acc[mi][ni][1] + bv.y, 0.0f);
            float e2 = fmaxf(acc[mi][ni][2] + bv.x, 0.0f);
            float e3 = fmaxf(acc[mi][ni][3] + bv.y, 0.0f);
            if (g == i_node)     { e0 = 0.0f; e1 = 0.0f; }
            if (g + 8 == i_node) { e2 = 0.0f; e3 = 0.0f; }
            s0[ni] = e0 + e2;
            s1[ni] = e1 + e3;
        }
#pragma unroll
        for (int ni = 0; ni < 8; ++ni) {
#pragma unroll
            for (int m = 4; m <= 16; m <<= 1) {
                s0[ni] += __shfl_xor_sync(0xffffffffu, s0[ni], m);
                s1[ni] += __shfl_xor_sync(0xffffffffu, s1[ni], m);
            }
        }
        if (lane < 4) {
            int row = n * KK + i_node;
#pragma unroll
            for (int ni = 0; ni < 8; ++ni) {
                int col = warp_n * 64 + ni * 8 + lane * 2;
                const float2 hv = *(const float2*)(h + row * NH + col);
                *(float2*)(x + row * NH + col) = make_float2(hv.x + s0[ni], hv.y + s1[ni]);
            }
        }
    }
}

// ===========================================================================
// Output head
// ===========================================================================
__global__ void out_kernel(const float* __restrict__ t,
                           const float* __restrict__ Wo2,
                           const float* __restrict__ bo2,
                           float* __restrict__ out) {
    __shared__ float sig[16];
    const int n = blockIdx.x;
    const int w = threadIdx.x >> 5;
    const int l = threadIdx.x & 31;
    const float* row = t + (n * KK + w) * NH;
    float acc = 0.0f;
#pragma unroll
    for (int kk = l; kk < NH; kk += 32)
        acc = fmaf(row[kk], Wo2[kk], acc);
#pragma unroll
    for (int m = 16; m; m >>= 1)
        acc += __shfl_xor_sync(0xffffffffu, acc, m);
    if (l == 0) {
        float logit = acc + bo2[0];
        sig[w] = 1.0f / (1.0f + expf(-logit));
    }
    __syncthreads();
    if (threadIdx.x == 0) {
        float prodv = 1.0f;
#pragma unroll
        for (int i2 = 0; i2 < 16; ++i2) prodv *= sig[i2];
        out[n] = prodv;
    }
}

// ===========================================================================
extern "C" void kernel_launch(void* const* d_in, const int* in_sizes, int n_in,
                              void* d_out, int out_size) {
    const float* towers = (const float*)d_in[0];
    const float* We  = (const float*)d_in[1];
    const float* be  = (const float*)d_in[2];
    const float* Wm1 = (const float*)d_in[3];
    const float* bm1 = (const float*)d_in[4];
    const float* Wm2 = (const float*)d_in[5];
    const float* bm2 = (const float*)d_in[6];
    const float* Wu1 = (const float*)d_in[7];
    const float* bu1 = (const float*)d_in[8];
    const float* Wu2 = (const float*)d_in[9];
    const float* bu2 = (const float*)d_in[10];
    const float* Wo1 = (const float*)d_in[11];
    const float* bo1 = (const float*)d_in[12];
    const float* Wo2 = (const float*)d_in[13];
    const float* bo2 = (const float*)d_in[14];
    float* out = (float*)d_out;

    float *h, *pq, *x, *t, *bpq;
    __nv_bfloat16 *Bpqh, *Bpql, *Bu1h, *Bu1l, *Bu2h, *Bu2l, *Bo1h, *Bo1l;
    cudaGetSymbolAddress((void**)&h, g_h);
    cudaGetSymbolAddress((void**)&pq, g_pq);
    cudaGetSymbolAddress((void**)&x, g_x);
    cudaGetSymbolAddress((void**)&t, g_t);
    cudaGetSymbolAddress((void**)&bpq, g_bpq);
    cudaGetSymbolAddress((void**)&Bpqh, g_Bpqh);
    cudaGetSymbolAddress((void**)&Bpql, g_Bpql);
    cudaGetSymbolAddress((void**)&Bu1h, g_Bu1h);
    cudaGetSymbolAddress((void**)&Bu1l, g_Bu1l);
    cudaGetSymbolAddress((void**)&Bu2h, g_Bu2h);
    cudaGetSymbolAddress((void**)&Bu2l, g_Bu2l);
    cudaGetSymbolAddress((void**)&Bo1h, g_Bo1h);
    cudaGetSymbolAddress((void**)&Bo1l, g_Bo1l);

    cudaFuncSetAttribute(edge_mma_kernel,
                         cudaFuncAttributeMaxDynamicSharedMemorySize, E7_TOT);
    cudaFuncSetAttribute(hmma_gemm<2>,
                         cudaFuncAttributeMaxDynamicSharedMemorySize, GV_TOT(2));
    cudaFuncSetAttribute(hmma_gemm<1>,
                         cudaFuncAttributeMaxDynamicSharedMemorySize, GV_TOT(1));

    prep_encode_kernel<<<1536 + NR, 256>>>(Wm1, bm1, Wm2, Wu1, Wu2, Wo1,
                                           towers, We, be, h);

    for (int it = 0; it < 3; ++it) {
        // pq = h @ [Wm1_s | Wm1_r] + [bm1|0]   (M=8192, N=512, BM=64)
        hmma_gemm<2><<<dim3(2, 128), 256, GV_TOT(2)>>>(h, Bpqh, Bpql, bpq, pq, 512, 0);
        // x = h + masked edge sum
        edge_mma_kernel<<<dim3(NG, 4), 256, E7_TOT>>>(pq, bm2, h, x);
        // h = relu(x@Wu1+bu1) @ Wu2 + bu2   (BM=32 -> 256 CTAs, full wave)
        hmma_gemm<1><<<dim3(1, 256), 256, GV_TOT(1)>>>(x, Bu1h, Bu1l, bu1, t, 256, 1);
        hmma_gemm<1><<<dim3(1, 256), 256, GV_TOT(1)>>>(t, Bu2h, Bu2l, bu2, h, 256, 0);
    }
    hmma_gemm<1><<<dim3(1, 256), 256, GV_TOT(1)>>>(h, Bo1h, Bo1l, bo1, t, 256, 1);
    out_kernel<<<NG, 512>>>(t, Wo2, bo2, out);
}